// round 6
// baseline (speedup 1.0000x reference)
#include <cuda_runtime.h>
#include <cuda_fp16.h>
#include <cstdint>
#include <math.h>

// Problem constants
#define T_TOK 1024
#define H_DIM 1024
#define I_DIM 512
#define N_EXP 16
#define TOPK  4
#define NPAIR (T_TOK * TOPK)   // 4096

// ============================================================================
// Scratch (__device__ globals; allocations are forbidden)
// ============================================================================
__device__ int g_offset[N_EXP + 1];
__device__ int g_tok[NPAIR];
__device__ int g_pos_of[NPAIR];

__device__ __half g_Xh[T_TOK * H_DIM];
__device__ __half g_GUh[N_EXP * 2 * I_DIM * H_DIM];
__device__ __half g_GUl[N_EXP * 2 * I_DIM * H_DIM];
__device__ __half g_Dh[N_EXP * H_DIM * I_DIM];
__device__ __half g_Dl[N_EXP * H_DIM * I_DIM];
__device__ __half g_Hh[NPAIR * I_DIM];
__device__ float  g_pout[NPAIR * H_DIM];

// ============================================================================
// PTX helpers (sm_80-era: cp.async, ldmatrix, mma.sync — legal on compute_103)
// ============================================================================
__device__ __forceinline__ uint32_t smem_to_u32(const void* p) {
    uint32_t a;
    asm("{ .reg .u64 t; cvta.to.shared.u64 t, %1; cvt.u32.u64 %0, t; }" : "=r"(a) : "l"(p));
    return a;
}
__device__ __forceinline__ void cp16(uint32_t saddr, const void* g, int szbytes) {
    asm volatile("cp.async.cg.shared.global [%0], [%1], 16, %2;"
                 :: "r"(saddr), "l"(g), "r"(szbytes) : "memory");
}
#define CP_COMMIT() asm volatile("cp.async.commit_group;" ::: "memory")
#define CP_WAIT1()  asm volatile("cp.async.wait_group 1;" ::: "memory")
#define CP_WAIT0()  asm volatile("cp.async.wait_group 0;" ::: "memory")

__device__ __forceinline__ void ldsm_x4(uint32_t* r, uint32_t addr) {
    asm volatile("ldmatrix.sync.aligned.m8n8.x4.shared.b16 {%0,%1,%2,%3}, [%4];"
                 : "=r"(r[0]), "=r"(r[1]), "=r"(r[2]), "=r"(r[3]) : "r"(addr));
}
__device__ __forceinline__ void mma16816(float* c, const uint32_t* a, uint32_t b0, uint32_t b1) {
    asm volatile(
        "mma.sync.aligned.m16n8k16.row.col.f32.f16.f16.f32 "
        "{%0,%1,%2,%3}, {%4,%5,%6,%7}, {%8,%9}, {%0,%1,%2,%3};"
        : "+f"(c[0]), "+f"(c[1]), "+f"(c[2]), "+f"(c[3])
        : "r"(a[0]), "r"(a[1]), "r"(a[2]), "r"(a[3]), "r"(b0), "r"(b1));
}

// Tile smem: [128 rows][64 fp16] = 128B/row, 8x 16B chunks/row, chunk' = chunk ^ (row&7)
// Stage layout: A_hi | B_hi | B_lo, each 128x64 fp16 = 16KB
#define SA_HI 0
#define SB_HI 16384
#define SB_LO 32768
#define ST_SZ 49152
#define SM_TOTAL (2 * ST_SZ)   // 96KB

// ============================================================================
// Routing: single-block count -> prefix -> scatter (1 launch)
// ============================================================================
__global__ void routing_kernel(const int* __restrict__ idx) {
    __shared__ int cnt[N_EXP];
    __shared__ int off[N_EXP];
    const int tid = threadIdx.x;   // 256 threads
    if (tid < N_EXP) cnt[tid] = 0;
    __syncthreads();
    #pragma unroll
    for (int j = 0; j < NPAIR / 256; j++)
        atomicAdd(&cnt[idx[tid + j * 256]], 1);
    __syncthreads();
    if (tid == 0) {
        int acc = 0;
        for (int e = 0; e < N_EXP; e++) { off[e] = acc; g_offset[e] = acc; acc += cnt[e]; }
        g_offset[N_EXP] = acc;
    }
    __syncthreads();
    if (tid < N_EXP) cnt[tid] = 0;
    __syncthreads();
    #pragma unroll
    for (int j = 0; j < NPAIR / 256; j++) {
        const int i = tid + j * 256;
        const int e = idx[i];
        const int pos = off[e] + atomicAdd(&cnt[e], 1);
        g_tok[pos]  = i >> 2;
        g_pos_of[i] = pos;
    }
}

// ============================================================================
// Fused fp32 -> fp16 splits (gate_up hi/lo, down hi/lo, hidden hi) in 1 launch
// ============================================================================
#define N4G (N_EXP * 2 * I_DIM * H_DIM / 4)   // 4194304
#define N4D (N_EXP * H_DIM * I_DIM / 4)       // 2097152
#define N4X (T_TOK * H_DIM / 4)               // 262144
__global__ void split_all_kernel(const float* __restrict__ gu,
                                 const float* __restrict__ dn,
                                 const float* __restrict__ x) {
    const int i = blockIdx.x * blockDim.x + threadIdx.x;
    const float* src;
    __half *hi, *lo = nullptr;
    int j;
    if (i < N4G)            { src = gu; j = i;              hi = g_GUh; lo = g_GUl; }
    else if (i < N4G + N4D) { src = dn; j = i - N4G;        hi = g_Dh;  lo = g_Dl;  }
    else if (i < N4G + N4D + N4X) { src = x; j = i - N4G - N4D; hi = g_Xh; }
    else return;
    float4 v = ((const float4*)src)[j];
    float f[4] = {v.x, v.y, v.z, v.w};
    __half h[4];
    #pragma unroll
    for (int q = 0; q < 4; q++) h[q] = __float2half_rn(f[q]);
    uint32_t hp0 = (uint32_t)__half_as_ushort(h[0]) | ((uint32_t)__half_as_ushort(h[1]) << 16);
    uint32_t hp1 = (uint32_t)__half_as_ushort(h[2]) | ((uint32_t)__half_as_ushort(h[3]) << 16);
    ((uint2*)hi)[j] = make_uint2(hp0, hp1);
    if (lo) {
        __half l[4];
        #pragma unroll
        for (int q = 0; q < 4; q++) l[q] = __float2half_rn(f[q] - __half2float(h[q]));
        uint32_t lp0 = (uint32_t)__half_as_ushort(l[0]) | ((uint32_t)__half_as_ushort(l[1]) << 16);
        uint32_t lp1 = (uint32_t)__half_as_ushort(l[2]) | ((uint32_t)__half_as_ushort(l[3]) << 16);
        ((uint2*)lo)[j] = make_uint2(lp0, lp1);
    }
}

// ============================================================================
// GEMM1: 128 pairs x 64 I-cols (gate/up interleaved as 128 B-rows), K = 1024
// 2-pass fp16 (A_hi*(B_hi+B_lo)), ldmatrix frags, K-chunk 64, double buffer.
// ============================================================================
__global__ __launch_bounds__(256) void gemm1_mma() {
    const int e     = blockIdx.z;
    const int start = g_offset[e];
    const int nrows = g_offset[e + 1] - start;
    const int row0  = blockIdx.y * 128;
    if (row0 >= nrows) return;
    const int col0 = blockIdx.x * 64;

    extern __shared__ char smem[];
    const uint32_t sbu = smem_to_u32(smem);
    const int tid  = threadIdx.x;
    const int wid  = tid >> 5, lane = tid & 31;
    const int g    = lane >> 2, tg = lane & 3;
    const int wm   = wid & 3, wn = wid >> 2;

    // loader: thread t owns row lr = t>>1, chunks lc..lc+3 (lc = (t&1)*4)
    const int lr = tid >> 1;
    const int lc = (tid & 1) * 4;
    const bool v0 = (row0 + lr) < nrows;
    const int tok0 = v0 ? g_tok[start + row0 + lr] : 0;
    const __half* aptr = g_Xh + (size_t)tok0 * H_DIM;
    const size_t brow = ((size_t)e * 1024 + col0 + (lr >> 1) + (lr & 1) * 512) * H_DIM;
    uint32_t so[4];
    #pragma unroll
    for (int j = 0; j < 4; j++) so[j] = (uint32_t)(lr * 128 + (((lc + j) ^ (lr & 7)) << 4));

    // mma lane geometry
    const int quad = lane >> 3, lr8 = lane & 7;
    const int a_r  = wm * 32 + (quad & 1) * 8 + lr8;   // + mt*16
    const int a_k8 = quad >> 1;
    const int b_rb = wn * 64 + (quad >> 1) * 8 + lr8;  // + ntp*16
    const int b_k8 = quad & 1;
    const uint32_t arx = (uint32_t)(a_r & 7);
    const uint32_t brx = (uint32_t)(b_rb & 7);
    uint32_t abase[2], bbase[4];
    #pragma unroll
    for (int mt = 0; mt < 2; mt++) abase[mt] = (uint32_t)((a_r + mt * 16) * 128);
    #pragma unroll
    for (int ntp = 0; ntp < 4; ntp++) bbase[ntp] = (uint32_t)((b_rb + ntp * 16) * 128);

    float acc[2][8][4];
    #pragma unroll
    for (int a = 0; a < 2; a++)
        #pragma unroll
        for (int b = 0; b < 8; b++)
            #pragma unroll
            for (int c = 0; c < 4; c++) acc[a][b][c] = 0.f;

    const int NCH = H_DIM / 64;   // 16
    {
        uint32_t s = sbu;
        #pragma unroll
        for (int j = 0; j < 4; j++) {
            const int eo = (lc + j) * 8;
            cp16(s + SA_HI + so[j], aptr + eo, v0 ? 16 : 0);
            cp16(s + SB_HI + so[j], g_GUh + brow + eo, 16);
            cp16(s + SB_LO + so[j], g_GUl + brow + eo, 16);
        }
        CP_COMMIT();
    }

    #pragma unroll 1
    for (int ch = 0; ch < NCH; ch++) {
        if (ch + 1 < NCH) {
            const int kb = (ch + 1) * 64;
            uint32_t s = sbu + ((ch + 1) & 1) * ST_SZ;
            #pragma unroll
            for (int j = 0; j < 4; j++) {
                const int eo = kb + (lc + j) * 8;
                cp16(s + SA_HI + so[j], aptr + eo, v0 ? 16 : 0);
                cp16(s + SB_HI + so[j], g_GUh + brow + eo, 16);
                cp16(s + SB_LO + so[j], g_GUl + brow + eo, 16);
            }
            CP_COMMIT();
            CP_WAIT1();
        } else {
            CP_WAIT0();
        }
        __syncthreads();
        const uint32_t st = sbu + (ch & 1) * ST_SZ;
        #pragma unroll
        for (int kh8 = 0; kh8 < 8; kh8 += 2) {
            uint32_t Ah[2][4];
            #pragma unroll
            for (int mt = 0; mt < 2; mt++)
                ldsm_x4(Ah[mt], st + SA_HI + abase[mt] + ((((uint32_t)(kh8 + a_k8)) ^ arx) << 4));
            #pragma unroll
            for (int ntp = 0; ntp < 4; ntp++) {
                uint32_t Bh[4], Bl[4];
                const uint32_t bo = bbase[ntp] + ((((uint32_t)(kh8 + b_k8)) ^ brx) << 4);
                ldsm_x4(Bh, st + SB_HI + bo);
                ldsm_x4(Bl, st + SB_LO + bo);
                #pragma unroll
                for (int mt = 0; mt < 2; mt++) {
                    mma16816(acc[mt][2 * ntp],     Ah[mt], Bh[0], Bh[1]);
                    mma16816(acc[mt][2 * ntp],     Ah[mt], Bl[0], Bl[1]);
                    mma16816(acc[mt][2 * ntp + 1], Ah[mt], Bh[2], Bh[3]);
                    mma16816(acc[mt][2 * ntp + 1], Ah[mt], Bl[2], Bl[3]);
                }
            }
        }
        __syncthreads();
    }

    // Epilogue: (c0,c1)=(gate,up) of one logical col; silu fuse; fp16 store.
    #pragma unroll
    for (int mt = 0; mt < 2; mt++) {
        #pragma unroll
        for (int nt = 0; nt < 8; nt++) {
            const int r  = wm * 32 + mt * 16 + g;
            const int jj = col0 + ((wn * 64 + nt * 8 + tg * 2) >> 1);
            const float* c = acc[mt][nt];
            #pragma unroll
            for (int hrow = 0; hrow < 2; hrow++) {
                const int rr = r + hrow * 8;
                if (row0 + rr < nrows) {
                    const float gate = c[hrow * 2], up = c[hrow * 2 + 1];
                    const float h = gate / (1.f + __expf(-gate)) * up;
                    g_Hh[(size_t)(start + row0 + rr) * I_DIM + jj] = __float2half_rn(h);
                }
            }
        }
    }
}

// ============================================================================
// GEMM2: 128 pairs x 128 H-cols, K = 512, same scheme -> g_pout (fp32)
// ============================================================================
__global__ __launch_bounds__(256) void gemm2_mma() {
    const int e     = blockIdx.z;
    const int start = g_offset[e];
    const int nrows = g_offset[e + 1] - start;
    const int row0  = blockIdx.y * 128;
    if (row0 >= nrows) return;
    const int col0 = blockIdx.x * 128;

    extern __shared__ char smem[];
    const uint32_t sbu = smem_to_u32(smem);
    const int tid  = threadIdx.x;
    const int wid  = tid >> 5, lane = tid & 31;
    const int g    = lane >> 2, tg = lane & 3;
    const int wm   = wid & 3, wn = wid >> 2;

    const int lr = tid >> 1;
    const int lc = (tid & 1) * 4;
    const bool v0 = (row0 + lr) < nrows;
    const size_t arow = (size_t)(start + row0 + (v0 ? lr : 0)) * I_DIM;
    const size_t brow = ((size_t)e * H_DIM + col0 + lr) * I_DIM;
    uint32_t so[4];
    #pragma unroll
    for (int j = 0; j < 4; j++) so[j] = (uint32_t)(lr * 128 + (((lc + j) ^ (lr & 7)) << 4));

    const int quad = lane >> 3, lr8 = lane & 7;
    const int a_r  = wm * 32 + (quad & 1) * 8 + lr8;
    const int a_k8 = quad >> 1;
    const int b_rb = wn * 64 + (quad >> 1) * 8 + lr8;
    const int b_k8 = quad & 1;
    const uint32_t arx = (uint32_t)(a_r & 7);
    const uint32_t brx = (uint32_t)(b_rb & 7);
    uint32_t abase[2], bbase[4];
    #pragma unroll
    for (int mt = 0; mt < 2; mt++) abase[mt] = (uint32_t)((a_r + mt * 16) * 128);
    #pragma unroll
    for (int ntp = 0; ntp < 4; ntp++) bbase[ntp] = (uint32_t)((b_rb + ntp * 16) * 128);

    float acc[2][8][4];
    #pragma unroll
    for (int a = 0; a < 2; a++)
        #pragma unroll
        for (int b = 0; b < 8; b++)
            #pragma unroll
            for (int c = 0; c < 4; c++) acc[a][b][c] = 0.f;

    const int NCH = I_DIM / 64;   // 8
    {
        uint32_t s = sbu;
        #pragma unroll
        for (int j = 0; j < 4; j++) {
            const int eo = (lc + j) * 8;
            cp16(s + SA_HI + so[j], g_Hh + arow + eo, v0 ? 16 : 0);
            cp16(s + SB_HI + so[j], g_Dh + brow + eo, 16);
            cp16(s + SB_LO + so[j], g_Dl + brow + eo, 16);
        }
        CP_COMMIT();
    }

    #pragma unroll 1
    for (int ch = 0; ch < NCH; ch++) {
        if (ch + 1 < NCH) {
            const int kb = (ch + 1) * 64;
            uint32_t s = sbu + ((ch + 1) & 1) * ST_SZ;
            #pragma unroll
            for (int j = 0; j < 4; j++) {
                const int eo = kb + (lc + j) * 8;
                cp16(s + SA_HI + so[j], g_Hh + arow + eo, v0 ? 16 : 0);
                cp16(s + SB_HI + so[j], g_Dh + brow + eo, 16);
                cp16(s + SB_LO + so[j], g_Dl + brow + eo, 16);
            }
            CP_COMMIT();
            CP_WAIT1();
        } else {
            CP_WAIT0();
        }
        __syncthreads();
        const uint32_t st = sbu + (ch & 1) * ST_SZ;
        #pragma unroll
        for (int kh8 = 0; kh8 < 8; kh8 += 2) {
            uint32_t Ah[2][4];
            #pragma unroll
            for (int mt = 0; mt < 2; mt++)
                ldsm_x4(Ah[mt], st + SA_HI + abase[mt] + ((((uint32_t)(kh8 + a_k8)) ^ arx) << 4));
            #pragma unroll
            for (int ntp = 0; ntp < 4; ntp++) {
                uint32_t Bh[4], Bl[4];
                const uint32_t bo = bbase[ntp] + ((((uint32_t)(kh8 + b_k8)) ^ brx) << 4);
                ldsm_x4(Bh, st + SB_HI + bo);
                ldsm_x4(Bl, st + SB_LO + bo);
                #pragma unroll
                for (int mt = 0; mt < 2; mt++) {
                    mma16816(acc[mt][2 * ntp],     Ah[mt], Bh[0], Bh[1]);
                    mma16816(acc[mt][2 * ntp],     Ah[mt], Bl[0], Bl[1]);
                    mma16816(acc[mt][2 * ntp + 1], Ah[mt], Bh[2], Bh[3]);
                    mma16816(acc[mt][2 * ntp + 1], Ah[mt], Bl[2], Bl[3]);
                }
            }
        }
        __syncthreads();
    }

    #pragma unroll
    for (int mt = 0; mt < 2; mt++) {
        #pragma unroll
        for (int nt = 0; nt < 8; nt++) {
            const int r   = wm * 32 + mt * 16 + g;
            const int col = col0 + wn * 64 + nt * 8 + tg * 2;
            const float* c = acc[mt][nt];
            #pragma unroll
            for (int hrow = 0; hrow < 2; hrow++) {
                const int rr = r + hrow * 8;
                if (row0 + rr < nrows) {
                    float2 v = make_float2(c[hrow * 2], c[hrow * 2 + 1]);
                    *(float2*)(g_pout + (size_t)(start + row0 + rr) * H_DIM + col) = v;
                }
            }
        }
    }
}

// ============================================================================
// Reduce: out[t,h] = sum_k w[t,k] * g_pout[pos_of[t,k], h]  (deterministic)
// ============================================================================
__global__ void reduce_kernel(const float* __restrict__ wts, float* __restrict__ out) {
    const int i = blockIdx.x * blockDim.x + threadIdx.x;
    if (i >= T_TOK * H_DIM / 4) return;
    const int t  = i / (H_DIM / 4);
    const int h4 = (i % (H_DIM / 4)) * 4;
    float4 acc = make_float4(0.f, 0.f, 0.f, 0.f);
    #pragma unroll
    for (int k = 0; k < TOPK; k++) {
        const int   pos = g_pos_of[t * TOPK + k];
        const float w   = wts[t * TOPK + k];
        const float4 v  = *(const float4*)(g_pout + (size_t)pos * H_DIM + h4);
        acc.x = fmaf(w, v.x, acc.x);
        acc.y = fmaf(w, v.y, acc.y);
        acc.z = fmaf(w, v.z, acc.z);
        acc.w = fmaf(w, v.w, acc.w);
    }
    *(float4*)(out + (size_t)t * H_DIM + h4) = acc;
}

// ============================================================================
// Launch (graph-capturable: kernel launches only)
// ============================================================================
extern "C" void kernel_launch(void* const* d_in, const int* in_sizes, int n_in,
                              void* d_out, int out_size)
{
    const float* hidden  = (const float*)d_in[0];
    const int*   idx     = (const int*)  d_in[1];
    const float* wts     = (const float*)d_in[2];
    const float* gate_up = (const float*)d_in[3];
    const float* down    = (const float*)d_in[4];
    float*       out     = (float*)d_out;

    static bool attr_done = false;
    if (!attr_done) {
        cudaFuncSetAttribute(gemm1_mma, cudaFuncAttributeMaxDynamicSharedMemorySize, SM_TOTAL);
        cudaFuncSetAttribute(gemm2_mma, cudaFuncAttributeMaxDynamicSharedMemorySize, SM_TOTAL);
        attr_done = true;
    }

    routing_kernel<<<1, 256>>>(idx);

    const int n4all = N4G + N4D + N4X;
    split_all_kernel<<<(n4all + 255) / 256, 256>>>(gate_up, down, hidden);

    dim3 g1(I_DIM / 64, NPAIR / 128, N_EXP);
    gemm1_mma<<<g1, 256, SM_TOTAL>>>();

    dim3 g2(H_DIM / 128, NPAIR / 128, N_EXP);
    gemm2_mma<<<g2, 256, SM_TOTAL>>>();

    reduce_kernel<<<(T_TOK * H_DIM / 4 + 255) / 256, 256>>>(wts, out);
}

// round 8
// speedup vs baseline: 1.4654x; 1.4654x over previous
#include <cuda_runtime.h>
#include <cuda_fp16.h>
#include <cstdint>
#include <math.h>

// Problem constants
#define T_TOK 1024
#define H_DIM 1024
#define I_DIM 512
#define N_EXP 16
#define TOPK  4
#define NPAIR (T_TOK * TOPK)   // 4096

// ============================================================================
// Scratch (__device__ globals; allocations are forbidden)
// ============================================================================
__device__ int g_offset[N_EXP + 1];
__device__ int g_tok[NPAIR];
__device__ int g_pos_of[NPAIR];

__device__ __half g_Xh[T_TOK * H_DIM];               // hidden, fp16
__device__ __half g_GUh[N_EXP * 2 * I_DIM * H_DIM];  // gate_up, fp16 (single)
__device__ __half g_Dh[N_EXP * H_DIM * I_DIM];       // down hi
__device__ __half g_Dl[N_EXP * H_DIM * I_DIM];       // down lo
__device__ __half g_Hh[NPAIR * I_DIM];               // silu(g)*u, fp16
__device__ float  g_pout[NPAIR * H_DIM];

// ============================================================================
// PTX helpers (sm_80-era: cp.async, ldmatrix, mma.sync — legal on compute_103)
// ============================================================================
__device__ __forceinline__ uint32_t smem_to_u32(const void* p) {
    uint32_t a;
    asm("{ .reg .u64 t; cvta.to.shared.u64 t, %1; cvt.u32.u64 %0, t; }" : "=r"(a) : "l"(p));
    return a;
}
__device__ __forceinline__ void cp16(uint32_t saddr, const void* g, int szbytes) {
    asm volatile("cp.async.cg.shared.global [%0], [%1], 16, %2;"
                 :: "r"(saddr), "l"(g), "r"(szbytes) : "memory");
}
#define CP_COMMIT() asm volatile("cp.async.commit_group;" ::: "memory")
#define CP_WAIT1()  asm volatile("cp.async.wait_group 1;" ::: "memory")
#define CP_WAIT0()  asm volatile("cp.async.wait_group 0;" ::: "memory")

__device__ __forceinline__ void ldsm_x4(uint32_t* r, uint32_t addr) {
    asm volatile("ldmatrix.sync.aligned.m8n8.x4.shared.b16 {%0,%1,%2,%3}, [%4];"
                 : "=r"(r[0]), "=r"(r[1]), "=r"(r[2]), "=r"(r[3]) : "r"(addr));
}
__device__ __forceinline__ void mma16816(float* c, const uint32_t* a, uint32_t b0, uint32_t b1) {
    asm volatile(
        "mma.sync.aligned.m16n8k16.row.col.f32.f16.f16.f32 "
        "{%0,%1,%2,%3}, {%4,%5,%6,%7}, {%8,%9}, {%0,%1,%2,%3};"
        : "+f"(c[0]), "+f"(c[1]), "+f"(c[2]), "+f"(c[3])
        : "r"(a[0]), "r"(a[1]), "r"(a[2]), "r"(a[3]), "r"(b0), "r"(b1));
}

// Tile smem: [128 rows][32 fp16] = 64B/row, 4x 16B chunks/row, chunk' = chunk ^ (row&3)
// GEMM1 stage: A | B_hi       (2 x 8KB = 16KB), double-buffered 32KB
// GEMM2 stage: A | B_hi | B_lo (3 x 8KB = 24KB), double-buffered 48KB
#define SA    0
#define SBH   8192
#define SBL   16384
#define G1_ST 16384
#define G1_TOTAL (2 * G1_ST)
#define G2_ST 24576
#define G2_TOTAL (2 * G2_ST)

// ============================================================================
// Routing: single-block count -> prefix -> scatter (1 launch)
// ============================================================================
__global__ void routing_kernel(const int* __restrict__ idx) {
    __shared__ int cnt[N_EXP];
    __shared__ int off[N_EXP];
    const int tid = threadIdx.x;   // 256 threads
    if (tid < N_EXP) cnt[tid] = 0;
    __syncthreads();
    #pragma unroll
    for (int j = 0; j < NPAIR / 256; j++)
        atomicAdd(&cnt[idx[tid + j * 256]], 1);
    __syncthreads();
    if (tid == 0) {
        int acc = 0;
        for (int e = 0; e < N_EXP; e++) { off[e] = acc; g_offset[e] = acc; acc += cnt[e]; }
        g_offset[N_EXP] = acc;
    }
    __syncthreads();
    if (tid < N_EXP) cnt[tid] = 0;
    __syncthreads();
    #pragma unroll
    for (int j = 0; j < NPAIR / 256; j++) {
        const int i = tid + j * 256;
        const int e = idx[i];
        const int pos = off[e] + atomicAdd(&cnt[e], 1);
        g_tok[pos]  = i >> 2;
        g_pos_of[i] = pos;
    }
}

// ============================================================================
// Fused fp32 -> fp16 split: gate_up (hi only), down (hi+lo), hidden (hi only)
// ============================================================================
#define N4G (N_EXP * 2 * I_DIM * H_DIM / 4)   // 4194304
#define N4D (N_EXP * H_DIM * I_DIM / 4)       // 2097152
#define N4X (T_TOK * H_DIM / 4)               // 262144
__global__ void split_all_kernel(const float* __restrict__ gu,
                                 const float* __restrict__ dn,
                                 const float* __restrict__ x) {
    const int i = blockIdx.x * blockDim.x + threadIdx.x;
    const float* src;
    __half *hi, *lo = nullptr;
    int j;
    if (i < N4G)                  { src = gu; j = i;              hi = g_GUh;             }
    else if (i < N4G + N4D)       { src = dn; j = i - N4G;        hi = g_Dh;  lo = g_Dl;  }
    else if (i < N4G + N4D + N4X) { src = x;  j = i - N4G - N4D;  hi = g_Xh;              }
    else return;
    float4 v = ((const float4*)src)[j];
    float f[4] = {v.x, v.y, v.z, v.w};
    __half h[4];
    #pragma unroll
    for (int q = 0; q < 4; q++) h[q] = __float2half_rn(f[q]);
    uint32_t hp0 = (uint32_t)__half_as_ushort(h[0]) | ((uint32_t)__half_as_ushort(h[1]) << 16);
    uint32_t hp1 = (uint32_t)__half_as_ushort(h[2]) | ((uint32_t)__half_as_ushort(h[3]) << 16);
    ((uint2*)hi)[j] = make_uint2(hp0, hp1);
    if (lo) {
        __half l[4];
        #pragma unroll
        for (int q = 0; q < 4; q++) l[q] = __float2half_rn(f[q] - __half2float(h[q]));
        uint32_t lp0 = (uint32_t)__half_as_ushort(l[0]) | ((uint32_t)__half_as_ushort(l[1]) << 16);
        uint32_t lp1 = (uint32_t)__half_as_ushort(l[2]) | ((uint32_t)__half_as_ushort(l[3]) << 16);
        ((uint2*)lo)[j] = make_uint2(lp0, lp1);
    }
}

// ============================================================================
// GEMM1: 128 pairs x 64 I-cols (gate/up interleaved as 128 B-rows), K = 1024
// Single-pass fp16 (A * B_hi), ldmatrix frags, K-chunk 32, double buffer.
// Fused silu(gate)*up epilogue -> g_Hh (fp16).
// ============================================================================
__global__ __launch_bounds__(256) void gemm1_mma() {
    const int e     = blockIdx.z;
    const int start = g_offset[e];
    const int nrows = g_offset[e + 1] - start;
    const int row0  = blockIdx.y * 128;
    if (row0 >= nrows) return;
    const int col0 = blockIdx.x * 64;

    extern __shared__ char smem[];
    const uint32_t sbu = smem_to_u32(smem);
    const int tid  = threadIdx.x;
    const int wid  = tid >> 5, lane = tid & 31;
    const int g    = lane >> 2, tg = lane & 3;
    const int wm   = wid & 3, wn = wid >> 2;

    // loader: thread t owns row lr = t>>1, chunks lc, lc+1 (16B each) per matrix
    const int lr = tid >> 1;
    const int lc = (tid & 1) * 2;
    const bool v0 = (row0 + lr) < nrows;
    const int tok0 = v0 ? g_tok[start + row0 + lr] : 0;
    const __half* aptr = g_Xh + (size_t)tok0 * H_DIM;
    const size_t brow = ((size_t)e * 1024 + col0 + (lr >> 1) + (lr & 1) * 512) * H_DIM;
    uint32_t so[2];
    #pragma unroll
    for (int j = 0; j < 2; j++) so[j] = (uint32_t)(lr * 64 + (((lc + j) ^ (lr & 3)) << 4));

    // mma lane geometry (ldmatrix addressing)
    const int quad = lane >> 3, lr8 = lane & 7;
    const int a_r  = wm * 32 + (quad & 1) * 8 + lr8;   // + mt*16
    const int a_k8 = quad >> 1;
    const int b_rb = wn * 64 + (quad >> 1) * 8 + lr8;  // + ntp*16
    const int b_k8 = quad & 1;
    const uint32_t arx = (uint32_t)(a_r & 3);
    const uint32_t brx = (uint32_t)(b_rb & 3);
    uint32_t abase[2], bbase[4];
    #pragma unroll
    for (int mt = 0; mt < 2; mt++) abase[mt] = (uint32_t)((a_r + mt * 16) * 64);
    #pragma unroll
    for (int ntp = 0; ntp < 4; ntp++) bbase[ntp] = (uint32_t)((b_rb + ntp * 16) * 64);

    float acc[2][8][4];
    #pragma unroll
    for (int a = 0; a < 2; a++)
        #pragma unroll
        for (int b = 0; b < 8; b++)
            #pragma unroll
            for (int c = 0; c < 4; c++) acc[a][b][c] = 0.f;

    const int NCH = H_DIM / 32;   // 32
    {
        uint32_t s = sbu;
        #pragma unroll
        for (int j = 0; j < 2; j++) {
            const int eo = (lc + j) * 8;
            cp16(s + SA  + so[j], aptr + eo, v0 ? 16 : 0);
            cp16(s + SBH + so[j], g_GUh + brow + eo, 16);
        }
        CP_COMMIT();
    }

    #pragma unroll 1
    for (int ch = 0; ch < NCH; ch++) {
        if (ch + 1 < NCH) {
            const int kb = (ch + 1) * 32;
            uint32_t s = sbu + ((ch + 1) & 1) * G1_ST;
            #pragma unroll
            for (int j = 0; j < 2; j++) {
                const int eo = kb + (lc + j) * 8;
                cp16(s + SA  + so[j], aptr + eo, v0 ? 16 : 0);
                cp16(s + SBH + so[j], g_GUh + brow + eo, 16);
            }
            CP_COMMIT();
            CP_WAIT1();
        } else {
            CP_WAIT0();
        }
        __syncthreads();
        const uint32_t st = sbu + (ch & 1) * G1_ST;
        #pragma unroll
        for (int kh8 = 0; kh8 < 4; kh8 += 2) {
            uint32_t Ah[2][4];
            #pragma unroll
            for (int mt = 0; mt < 2; mt++)
                ldsm_x4(Ah[mt], st + SA + abase[mt] + ((((uint32_t)(kh8 + a_k8)) ^ arx) << 4));
            #pragma unroll
            for (int ntp = 0; ntp < 4; ntp++) {
                uint32_t Bh[4];
                ldsm_x4(Bh, st + SBH + bbase[ntp] + ((((uint32_t)(kh8 + b_k8)) ^ brx) << 4));
                #pragma unroll
                for (int mt = 0; mt < 2; mt++) {
                    mma16816(acc[mt][2 * ntp],     Ah[mt], Bh[0], Bh[1]);
                    mma16816(acc[mt][2 * ntp + 1], Ah[mt], Bh[2], Bh[3]);
                }
            }
        }
        __syncthreads();
    }

    // Epilogue: (c0,c1)=(gate,up) of one logical col; silu fuse; fp16 store.
    #pragma unroll
    for (int mt = 0; mt < 2; mt++) {
        #pragma unroll
        for (int nt = 0; nt < 8; nt++) {
            const int r  = wm * 32 + mt * 16 + g;
            const int jj = col0 + ((wn * 64 + nt * 8 + tg * 2) >> 1);
            const float* c = acc[mt][nt];
            #pragma unroll
            for (int hrow = 0; hrow < 2; hrow++) {
                const int rr = r + hrow * 8;
                if (row0 + rr < nrows) {
                    const float gate = c[hrow * 2], up = c[hrow * 2 + 1];
                    const float h = gate / (1.f + __expf(-gate)) * up;
                    g_Hh[(size_t)(start + row0 + rr) * I_DIM + jj] = __float2half_rn(h);
                }
            }
        }
    }
}

// ============================================================================
// GEMM2: 128 pairs x 128 H-cols, K = 512, 2-pass fp16 (A*(B_hi+B_lo))
// ldmatrix frags, K-chunk 32, double buffer -> g_pout (fp32)
// ============================================================================
__global__ __launch_bounds__(256) void gemm2_mma() {
    const int e     = blockIdx.z;
    const int start = g_offset[e];
    const int nrows = g_offset[e + 1] - start;
    const int row0  = blockIdx.y * 128;
    if (row0 >= nrows) return;
    const int col0 = blockIdx.x * 128;

    extern __shared__ char smem[];
    const uint32_t sbu = smem_to_u32(smem);
    const int tid  = threadIdx.x;
    const int wid  = tid >> 5, lane = tid & 31;
    const int g    = lane >> 2, tg = lane & 3;
    const int wm   = wid & 3, wn = wid >> 2;

    const int lr = tid >> 1;
    const int lc = (tid & 1) * 2;
    const bool v0 = (row0 + lr) < nrows;
    const size_t arow = (size_t)(start + row0 + (v0 ? lr : 0)) * I_DIM;
    const size_t brow = ((size_t)e * H_DIM + col0 + lr) * I_DIM;
    uint32_t so[2];
    #pragma unroll
    for (int j = 0; j < 2; j++) so[j] = (uint32_t)(lr * 64 + (((lc + j) ^ (lr & 3)) << 4));

    const int quad = lane >> 3, lr8 = lane & 7;
    const int a_r  = wm * 32 + (quad & 1) * 8 + lr8;
    const int a_k8 = quad >> 1;
    const int b_rb = wn * 64 + (quad >> 1) * 8 + lr8;
    const int b_k8 = quad & 1;
    const uint32_t arx = (uint32_t)(a_r & 3);
    const uint32_t brx = (uint32_t)(b_rb & 3);
    uint32_t abase[2], bbase[4];
    #pragma unroll
    for (int mt = 0; mt < 2; mt++) abase[mt] = (uint32_t)((a_r + mt * 16) * 64);
    #pragma unroll
    for (int ntp = 0; ntp < 4; ntp++) bbase[ntp] = (uint32_t)((b_rb + ntp * 16) * 64);

    float acc[2][8][4];
    #pragma unroll
    for (int a = 0; a < 2; a++)
        #pragma unroll
        for (int b = 0; b < 8; b++)
            #pragma unroll
            for (int c = 0; c < 4; c++) acc[a][b][c] = 0.f;

    const int NCH = I_DIM / 32;   // 16
    {
        uint32_t s = sbu;
        #pragma unroll
        for (int j = 0; j < 2; j++) {
            const int eo = (lc + j) * 8;
            cp16(s + SA  + so[j], g_Hh + arow + eo, v0 ? 16 : 0);
            cp16(s + SBH + so[j], g_Dh + brow + eo, 16);
            cp16(s + SBL + so[j], g_Dl + brow + eo, 16);
        }
        CP_COMMIT();
    }

    #pragma unroll 1
    for (int ch = 0; ch < NCH; ch++) {
        if (ch + 1 < NCH) {
            const int kb = (ch + 1) * 32;
            uint32_t s = sbu + ((ch + 1) & 1) * G2_ST;
            #pragma unroll
            for (int j = 0; j < 2; j++) {
                const int eo = kb + (lc + j) * 8;
                cp16(s + SA  + so[j], g_Hh + arow + eo, v0 ? 16 : 0);
                cp16(s + SBH + so[j], g_Dh + brow + eo, 16);
                cp16(s + SBL + so[j], g_Dl + brow + eo, 16);
            }
            CP_COMMIT();
            CP_WAIT1();
        } else {
            CP_WAIT0();
        }
        __syncthreads();
        const uint32_t st = sbu + (ch & 1) * G2_ST;
        #pragma unroll
        for (int kh8 = 0; kh8 < 4; kh8 += 2) {
            uint32_t Ah[2][4];
            #pragma unroll
            for (int mt = 0; mt < 2; mt++)
                ldsm_x4(Ah[mt], st + SA + abase[mt] + ((((uint32_t)(kh8 + a_k8)) ^ arx) << 4));
            #pragma unroll
            for (int ntp = 0; ntp < 4; ntp++) {
                uint32_t Bh[4], Bl[4];
                const uint32_t bo = bbase[ntp] + ((((uint32_t)(kh8 + b_k8)) ^ brx) << 4);
                ldsm_x4(Bh, st + SBH + bo);
                ldsm_x4(Bl, st + SBL + bo);
                #pragma unroll
                for (int mt = 0; mt < 2; mt++) {
                    mma16816(acc[mt][2 * ntp],     Ah[mt], Bh[0], Bh[1]);
                    mma16816(acc[mt][2 * ntp],     Ah[mt], Bl[0], Bl[1]);
                    mma16816(acc[mt][2 * ntp + 1], Ah[mt], Bh[2], Bh[3]);
                    mma16816(acc[mt][2 * ntp + 1], Ah[mt], Bl[2], Bl[3]);
                }
            }
        }
        __syncthreads();
    }

    #pragma unroll
    for (int mt = 0; mt < 2; mt++) {
        #pragma unroll
        for (int nt = 0; nt < 8; nt++) {
            const int r   = wm * 32 + mt * 16 + g;
            const int col = col0 + wn * 64 + nt * 8 + tg * 2;
            const float* c = acc[mt][nt];
            #pragma unroll
            for (int hrow = 0; hrow < 2; hrow++) {
                const int rr = r + hrow * 8;
                if (row0 + rr < nrows) {
                    float2 v = make_float2(c[hrow * 2], c[hrow * 2 + 1]);
                    *(float2*)(g_pout + (size_t)(start + row0 + rr) * H_DIM + col) = v;
                }
            }
        }
    }
}

// ============================================================================
// Reduce: out[t,h] = sum_k w[t,k] * g_pout[pos_of[t,k], h]  (deterministic)
// ============================================================================
__global__ void reduce_kernel(const float* __restrict__ wts, float* __restrict__ out) {
    const int i = blockIdx.x * blockDim.x + threadIdx.x;
    if (i >= T_TOK * H_DIM / 4) return;
    const int t  = i / (H_DIM / 4);
    const int h4 = (i % (H_DIM / 4)) * 4;
    float4 acc = make_float4(0.f, 0.f, 0.f, 0.f);
    #pragma unroll
    for (int k = 0; k < TOPK; k++) {
        const int   pos = g_pos_of[t * TOPK + k];
        const float w   = wts[t * TOPK + k];
        const float4 v  = *(const float4*)(g_pout + (size_t)pos * H_DIM + h4);
        acc.x = fmaf(w, v.x, acc.x);
        acc.y = fmaf(w, v.y, acc.y);
        acc.z = fmaf(w, v.z, acc.z);
        acc.w = fmaf(w, v.w, acc.w);
    }
    *(float4*)(out + (size_t)t * H_DIM + h4) = acc;
}

// ============================================================================
// Launch (graph-capturable: kernel launches only)
// ============================================================================
extern "C" void kernel_launch(void* const* d_in, const int* in_sizes, int n_in,
                              void* d_out, int out_size)
{
    const float* hidden  = (const float*)d_in[0];
    const int*   idx     = (const int*)  d_in[1];
    const float* wts     = (const float*)d_in[2];
    const float* gate_up = (const float*)d_in[3];
    const float* down    = (const float*)d_in[4];
    float*       out     = (float*)d_out;

    static bool attr_done = false;
    if (!attr_done) {
        cudaFuncSetAttribute(gemm1_mma, cudaFuncAttributeMaxDynamicSharedMemorySize, G1_TOTAL);
        cudaFuncSetAttribute(gemm2_mma, cudaFuncAttributeMaxDynamicSharedMemorySize, G2_TOTAL);
        attr_done = true;
    }

    routing_kernel<<<1, 256>>>(idx);

    const int n4all = N4G + N4D + N4X;
    split_all_kernel<<<(n4all + 255) / 256, 256>>>(gate_up, down, hidden);

    dim3 g1(I_DIM / 64, NPAIR / 128, N_EXP);
    gemm1_mma<<<g1, 256, G1_TOTAL>>>();

    dim3 g2(H_DIM / 128, NPAIR / 128, N_EXP);
    gemm2_mma<<<g2, 256, G2_TOTAL>>>();

    reduce_kernel<<<(T_TOK * H_DIM / 4 + 255) / 256, 256>>>(wts, out);
}